// round 10
// baseline (speedup 1.0000x reference)
#include <cuda_runtime.h>

// out[b,s,e] = sum_h cs[b,s,e,h] * W[e,h] + bias[e]
// B=4, S=512, E=64, H=1024 -> ROWS = 131072 reductions over 1024 contiguous floats.
//
// FINAL KERNEL (= R4, best measured: 77.9us, HBM 6.80 TB/s = 85.8% of spec).
// This problem is pure compulsory-traffic streaming: 512 MiB read once,
// 0.5 FLOP/byte. Across 6 measured variants (block sizes, row pairing,
// persistent grids, front-batched loads, 256-bit LDG, store hints) throughput
// pinned at 6.75-6.81 TB/s — the B300 practical HBM ceiling for this pattern
// (LTS chip-cap is path-independent; channel hash / refresh not addressable).
//
// Shape: one warp per row, fresh warp per row (per-warp tails hidden by
// co-resident warps — persistent loops serialize and regress), 64-thread CTAs
// for packing granularity, ld.global.cs for the one-pass stream, __ldg for the
// L1-resident W row, SHFL-chain warp reduce.

#define E_DIM 64
#define H_DIM 1024
#define HV4   (H_DIM / 4)      // 256 float4 per row
#define WARPS_PER_BLOCK 2

__device__ __forceinline__ float4 ldcs_f4(const float4* p) {
    float4 v;
    asm volatile("ld.global.cs.v4.f32 {%0,%1,%2,%3}, [%4];"
                 : "=f"(v.x), "=f"(v.y), "=f"(v.z), "=f"(v.w)
                 : "l"(p));
    return v;
}

__global__ __launch_bounds__(WARPS_PER_BLOCK * 32)
void Cell_to_Entity_78735340470739_kernel(
    const float4* __restrict__ cs,    // [ROWS, HV4]
    const float4* __restrict__ W,     // [E, HV4]
    const float*  __restrict__ bias,  // [E]
    float*        __restrict__ out)   // [ROWS]
{
    const int warp = threadIdx.x >> 5;
    const int lane = threadIdx.x & 31;
    const int row  = blockIdx.x * WARPS_PER_BLOCK + warp;

    const int e = row & (E_DIM - 1);

    const float4* __restrict__ x = cs + (size_t)row * HV4;
    const float4* __restrict__ w = W  + (size_t)e   * HV4;

    float acc = 0.0f;
#pragma unroll
    for (int i = 0; i < 8; ++i) {
        const int idx = lane + 32 * i;
        float4 a = ldcs_f4(&x[idx]);   // streaming, evict-first: one-pass data
        float4 b = __ldg(&w[idx]);     // hot in L1/L2 (256 KiB total W)
        acc += a.x * b.x + a.y * b.y + a.z * b.z + a.w * b.w;
    }

    // warp reduction
#pragma unroll
    for (int off = 16; off > 0; off >>= 1)
        acc += __shfl_xor_sync(0xffffffffu, acc, off);

    if (lane == 0)
        out[row] = acc + __ldg(&bias[e]);
}

extern "C" void kernel_launch(void* const* d_in, const int* in_sizes, int n_in,
                              void* d_out, int out_size)
{
    const float4* cs   = (const float4*)d_in[0];   // [B,S,E,H] float32
    const float4* W    = (const float4*)d_in[1];   // [E,H]     float32
    const float*  bias = (const float*)d_in[2];    // [E]       float32
    float*        out  = (float*)d_out;            // [B,S,E]   float32

    const int rows   = out_size;                   // B*S*E = 131072
    const int blocks = rows / WARPS_PER_BLOCK;     // 65536

    Cell_to_Entity_78735340470739_kernel<<<blocks, WARPS_PER_BLOCK * 32>>>(cs, W, bias, out);
}

// round 11
// speedup vs baseline: 1.0095x; 1.0095x over previous
#include <cuda_runtime.h>

// out[b,s,e] = sum_h cs[b,s,e,h] * W[e,h] + bias[e]
// B=4, S=512, E=64, H=1024 -> ROWS = 131072 reductions over 1024 contiguous floats.
//
// HBM-bound streaming pinned at the B300 practical ceiling (6.75-6.81 TB/s
// across 7 measured variants; run-to-run noise calibrated at +-0.7us on
// identical binaries). R10: final point on the block-size curve
// (256->128->64 gave DRAM 85.2->85.5->85.8%): 32-thread CTAs, one warp per
// CTA, finest packing/retirement granularity and minimal per-CTA L1tex burst.
// 32-CTA/SM cap binds warps at 32/SM (~50% occ) but achieved occ at 64-thr
// was only 53.8% and R5b showed extra occupancy is worthless here.

#define E_DIM 64
#define H_DIM 1024
#define HV4   (H_DIM / 4)      // 256 float4 per row

__device__ __forceinline__ float4 ldcs_f4(const float4* p) {
    float4 v;
    asm volatile("ld.global.cs.v4.f32 {%0,%1,%2,%3}, [%4];"
                 : "=f"(v.x), "=f"(v.y), "=f"(v.z), "=f"(v.w)
                 : "l"(p));
    return v;
}

__global__ __launch_bounds__(32)
void Cell_to_Entity_78735340470739_kernel(
    const float4* __restrict__ cs,    // [ROWS, HV4]
    const float4* __restrict__ W,     // [E, HV4]
    const float*  __restrict__ bias,  // [E]
    float*        __restrict__ out)   // [ROWS]
{
    const int lane = threadIdx.x;         // 32-thread CTA = one warp
    const int row  = blockIdx.x;

    const int e = row & (E_DIM - 1);

    const float4* __restrict__ x = cs + (size_t)row * HV4;
    const float4* __restrict__ w = W  + (size_t)e   * HV4;

    float acc = 0.0f;
#pragma unroll
    for (int i = 0; i < 8; ++i) {
        const int idx = lane + 32 * i;
        float4 a = ldcs_f4(&x[idx]);   // streaming, evict-first: one-pass data
        float4 b = __ldg(&w[idx]);     // hot in L1/L2 (256 KiB total W)
        acc += a.x * b.x + a.y * b.y + a.z * b.z + a.w * b.w;
    }

    // warp reduction
#pragma unroll
    for (int off = 16; off > 0; off >>= 1)
        acc += __shfl_xor_sync(0xffffffffu, acc, off);

    if (lane == 0)
        out[row] = acc + __ldg(&bias[e]);
}

extern "C" void kernel_launch(void* const* d_in, const int* in_sizes, int n_in,
                              void* d_out, int out_size)
{
    const float4* cs   = (const float4*)d_in[0];   // [B,S,E,H] float32
    const float4* W    = (const float4*)d_in[1];   // [E,H]     float32
    const float*  bias = (const float*)d_in[2];    // [E]       float32
    float*        out  = (float*)d_out;            // [B,S,E]   float32

    const int rows = out_size;                     // B*S*E = 131072

    Cell_to_Entity_78735340470739_kernel<<<rows, 32>>>(cs, W, bias, out);
}

// round 12
// speedup vs baseline: 1.0170x; 1.0075x over previous
#include <cuda_runtime.h>

// out[b,s,e] = sum_h cs[b,s,e,h] * W[e,h] + bias[e]
// B=4, S=512, E=64, H=1024 -> ROWS = 131072 reductions over 1024 contiguous floats.
//
// FINAL KERNEL (tied-best measured: 77.86us, HBM 6.81 TB/s = 85.9% of spec).
// Pure compulsory-traffic streaming: 512 MiB read once, 0.5 FLOP/byte.
// 9 measured variants (block 32/64/128/256, 128/256-bit LDG, row pairing,
// persistent grids, front-batching, cache hints) all pin at 6.75-6.81 TB/s —
// the B300 practical HBM ceiling for this pattern. Occupancy 36%..67% is
// perf-invariant; the binding resource is the DRAM pipe itself.
//
// Shape: one warp per CTA, one row per warp (fresh warp per row — per-warp
// tails hidden by co-resident warps; persistent loops serialize and regress),
// ld.global.cs for the one-pass stream, __ldg for the L1/L2-resident W row,
// SHFL-chain warp reduce.

#define E_DIM 64
#define H_DIM 1024
#define HV4   (H_DIM / 4)      // 256 float4 per row

__device__ __forceinline__ float4 ldcs_f4(const float4* p) {
    float4 v;
    asm volatile("ld.global.cs.v4.f32 {%0,%1,%2,%3}, [%4];"
                 : "=f"(v.x), "=f"(v.y), "=f"(v.z), "=f"(v.w)
                 : "l"(p));
    return v;
}

__global__ __launch_bounds__(32)
void Cell_to_Entity_78735340470739_kernel(
    const float4* __restrict__ cs,    // [ROWS, HV4]
    const float4* __restrict__ W,     // [E, HV4]
    const float*  __restrict__ bias,  // [E]
    float*        __restrict__ out)   // [ROWS]
{
    const int lane = threadIdx.x;         // 32-thread CTA = one warp
    const int row  = blockIdx.x;

    const int e = row & (E_DIM - 1);

    const float4* __restrict__ x = cs + (size_t)row * HV4;
    const float4* __restrict__ w = W  + (size_t)e   * HV4;

    float acc = 0.0f;
#pragma unroll
    for (int i = 0; i < 8; ++i) {
        const int idx = lane + 32 * i;
        float4 a = ldcs_f4(&x[idx]);   // streaming, evict-first: one-pass data
        float4 b = __ldg(&w[idx]);     // hot in L1/L2 (256 KiB total W)
        acc += a.x * b.x + a.y * b.y + a.z * b.z + a.w * b.w;
    }

    // warp reduction
#pragma unroll
    for (int off = 16; off > 0; off >>= 1)
        acc += __shfl_xor_sync(0xffffffffu, acc, off);

    if (lane == 0)
        out[row] = acc + __ldg(&bias[e]);
}

extern "C" void kernel_launch(void* const* d_in, const int* in_sizes, int n_in,
                              void* d_out, int out_size)
{
    const float4* cs   = (const float4*)d_in[0];   // [B,S,E,H] float32
    const float4* W    = (const float4*)d_in[1];   // [E,H]     float32
    const float*  bias = (const float*)d_in[2];    // [E]       float32
    float*        out  = (float*)d_out;            // [B,S,E]   float32

    const int rows = out_size;                     // B*S*E = 131072

    Cell_to_Entity_78735340470739_kernel<<<rows, 32>>>(cs, W, bias, out);
}

// round 13
// speedup vs baseline: 1.0306x; 1.0134x over previous
#include <cuda_runtime.h>

// out[b,s,e] = sum_h cs[b,s,e,h] * W[e,h] + bias[e]
// B=4, S=512, E=64, H=1024 -> ROWS = 131072 reductions over 1024 contiguous floats.
//
// FINAL KERNEL (best measured: 77.28us; identical binary measured 3x at
// 77.28/77.86/77.86 -> +-0.7us noise band). Pure compulsory-traffic streaming:
// 512 MiB read once, 0.5 FLOP/byte. 10 measured variants (block 32/64/128/256,
// 128/256-bit LDG, row pairing, persistent grids, front-batching, cache hints)
// all pin at 6.75-6.81 TB/s — the B300 practical HBM ceiling for this pattern
// (LTS cap is path-independent; channel hash / refresh not software-addressable).
// Kernel transport efficiency vs its own measured ceiling: >=99%.
//
// Shape: one warp per CTA, one row per warp (fresh warp per row — per-warp
// tails hidden by co-resident warps; persistent loops serialize and regress),
// ld.global.cs for the one-pass stream, __ldg for the L1/L2-resident W row,
// SHFL-chain warp reduce.

#define E_DIM 64
#define H_DIM 1024
#define HV4   (H_DIM / 4)      // 256 float4 per row

__device__ __forceinline__ float4 ldcs_f4(const float4* p) {
    float4 v;
    asm volatile("ld.global.cs.v4.f32 {%0,%1,%2,%3}, [%4];"
                 : "=f"(v.x), "=f"(v.y), "=f"(v.z), "=f"(v.w)
                 : "l"(p));
    return v;
}

__global__ __launch_bounds__(32)
void Cell_to_Entity_78735340470739_kernel(
    const float4* __restrict__ cs,    // [ROWS, HV4]
    const float4* __restrict__ W,     // [E, HV4]
    const float*  __restrict__ bias,  // [E]
    float*        __restrict__ out)   // [ROWS]
{
    const int lane = threadIdx.x;         // 32-thread CTA = one warp
    const int row  = blockIdx.x;

    const int e = row & (E_DIM - 1);

    const float4* __restrict__ x = cs + (size_t)row * HV4;
    const float4* __restrict__ w = W  + (size_t)e   * HV4;

    float acc = 0.0f;
#pragma unroll
    for (int i = 0; i < 8; ++i) {
        const int idx = lane + 32 * i;
        float4 a = ldcs_f4(&x[idx]);   // streaming, evict-first: one-pass data
        float4 b = __ldg(&w[idx]);     // hot in L1/L2 (256 KiB total W)
        acc += a.x * b.x + a.y * b.y + a.z * b.z + a.w * b.w;
    }

    // warp reduction
#pragma unroll
    for (int off = 16; off > 0; off >>= 1)
        acc += __shfl_xor_sync(0xffffffffu, acc, off);

    if (lane == 0)
        out[row] = acc + __ldg(&bias[e]);
}

extern "C" void kernel_launch(void* const* d_in, const int* in_sizes, int n_in,
                              void* d_out, int out_size)
{
    const float4* cs   = (const float4*)d_in[0];   // [B,S,E,H] float32
    const float4* W    = (const float4*)d_in[1];   // [E,H]     float32
    const float*  bias = (const float*)d_in[2];    // [E]       float32
    float*        out  = (float*)d_out;            // [B,S,E]   float32

    const int rows = out_size;                     // B*S*E = 131072

    Cell_to_Entity_78735340470739_kernel<<<rows, 32>>>(cs, W, bias, out);
}